// round 5
// baseline (speedup 1.0000x reference)
#include <cuda_runtime.h>
#include <cuda_bf16.h>
#include <math.h>
#include <stdint.h>

#define NS 8192
#define HHD 512
#define G3 1536
#define EE 128
#define VV 128
#define SSTEPS 32
#define NCTA 128
#define CROWS 64

// smem byte offsets
#define SM_A 0
#define A_SPLIT 66560          // 64*520*2 bytes per split
#define SM_B 133120
#define B_STAGE 18432          // one 16KB unit padded: 128 rows * 144B
#define SM_BHN 206848          // 512 floats: b_hh n-gate part
#define SM_SCH 208896          // 64 ints
#define SM_ARGV 209152         // 256 floats
#define SM_ARGI 210176         // 256 ints
#define SMEM_TOT 211200

// ---------------- persistent device scratch ----------------
__device__ float g_gctx[(size_t)NS * G3];    // [n][1536], b_ih (+ b_hh r,z) folded
__device__ float g_fcctx[(size_t)NS * VV];   // [n][128], fc_b folded
__device__ float g_embgi[VV * G3];           // [c][1536]
__device__ float g_fcemb[VV * VV];           // [c][128]
__device__ float g_h[(size_t)NS * HHD];      // h_new staging (fp32)
__device__ __align__(128) __nv_bfloat16 g_wpack[12 * 8 * 2 * 8192];   // gh units
__device__ __align__(128) __nv_bfloat16 g_fcpack[8 * 2 * 8192];       // fc units
__device__ __align__(128) __nv_bfloat16 g_ctxpack[13 * 8 * 2 * 8192]; // ctx units

// ---------------- small helpers ----------------
__device__ __forceinline__ uint32_t smem_u32(const void* p) {
    uint32_t a;
    asm("{ .reg .u64 t; cvta.to.shared.u64 t, %1; cvt.u32.u64 %0, t; }" : "=r"(a) : "l"(p));
    return a;
}
__device__ __forceinline__ void ldsm4(uint32_t addr, uint32_t r[4]) {
    asm volatile("ldmatrix.sync.aligned.m8n8.x4.shared.b16 {%0,%1,%2,%3}, [%4];"
        : "=r"(r[0]), "=r"(r[1]), "=r"(r[2]), "=r"(r[3]) : "r"(addr));
}
__device__ __forceinline__ void mma16816(float* c, const uint32_t a[4], const uint32_t b[2]) {
    asm volatile("mma.sync.aligned.m16n8k16.row.col.f32.bf16.bf16.f32 "
        "{%0,%1,%2,%3}, {%4,%5,%6,%7}, {%8,%9}, {%0,%1,%2,%3};"
        : "+f"(c[0]), "+f"(c[1]), "+f"(c[2]), "+f"(c[3])
        : "r"(a[0]), "r"(a[1]), "r"(a[2]), "r"(a[3]), "r"(b[0]), "r"(b[1]));
}
__device__ __forceinline__ void cp16(uint32_t dst, const void* src) {
    asm volatile("cp.async.cg.shared.global [%0], [%1], 16;" :: "r"(dst), "l"(src));
}
#define CPCOMMIT() asm volatile("cp.async.commit_group;" ::: "memory")
__device__ __forceinline__ void bsplit(float v, unsigned short& h, unsigned short& l) {
    __nv_bfloat16 bh = __float2bfloat16(v);
    __nv_bfloat16 bl = __float2bfloat16(v - __bfloat162float(bh));
    h = __bfloat16_as_ushort(bh);
    l = __bfloat16_as_ushort(bl);
}

// ---------------- prep kernels ----------------
__global__ void pack_w_kernel(const float* __restrict__ W_hh) {
    int idx = blockIdx.x * 256 + threadIdx.x;
    if (idx >= G3 * HHD) return;
    int R = idx >> 9, C = idx & 511;
    int g = R >> 9, rem = R & 511, jt = rem >> 7, n = rem & 127;
    int kc = C >> 6, k = C & 63;
    int tile = jt * 3 + g;
    unsigned short h, l;
    bsplit(W_hh[idx], h, l);
    size_t base = ((size_t)(tile * 8 + kc) * 2) * 8192 + n * 64 + k;
    g_wpack[base] = __ushort_as_bfloat16(h);
    g_wpack[base + 8192] = __ushort_as_bfloat16(l);
}

__global__ void pack_fc_kernel(const float* __restrict__ fc_W) {
    int idx = blockIdx.x * 256 + threadIdx.x;
    if (idx >= VV * HHD) return;
    int v = idx >> 9, C = idx & 511;
    int kc = C >> 6, k = C & 63;
    unsigned short h, l;
    bsplit(fc_W[(size_t)v * 1152 + 640 + C], h, l);
    size_t base = ((size_t)kc * 2) * 8192 + v * 64 + k;
    g_fcpack[base] = __ushort_as_bfloat16(h);
    g_fcpack[base + 8192] = __ushort_as_bfloat16(l);
}

// pack W_ih[:,128:640] (rows 0..1535 -> tiles 0..11) and fc_W[:,128:640] (tile 12)
__global__ void pack_ctx_kernel(const float* __restrict__ W_ih,
                                const float* __restrict__ fc_W) {
    int idx = blockIdx.x * 256 + threadIdx.x;
    if (idx >= 1664 * 512) return;
    int r = idx >> 9, k = idx & 511;
    float w = (r < G3) ? W_ih[(size_t)r * 640 + 128 + k]
                       : fc_W[(size_t)(r - G3) * 1152 + 128 + k];
    int tl = r >> 7, n = r & 127, kc = k >> 6, kk = k & 63;
    unsigned short h, l;
    bsplit(w, h, l);
    size_t base = ((size_t)(tl * 8 + kc) * 2) * 8192 + n * 64 + kk;
    g_ctxpack[base] = __ushort_as_bfloat16(h);
    g_ctxpack[base + 8192] = __ushort_as_bfloat16(l);
}

__global__ __launch_bounds__(128)
void emb_kernel(const float* __restrict__ emb_table,
                const float* __restrict__ W_ih,
                const float* __restrict__ fc_W) {
    __shared__ float er[EE];
    int c = blockIdx.y;
    int tx = threadIdx.x;
    er[tx] = emb_table[c * EE + tx];
    __syncthreads();
    int col = blockIdx.x * 128 + tx;   // [0, 1664)
    const float* brow = (col < G3) ? (W_ih + (size_t)col * 640)
                                   : (fc_W + (size_t)(col - G3) * 1152);
    float acc = 0.f;
#pragma unroll 8
    for (int e = 0; e < EE; e += 4) {
        float4 b = *reinterpret_cast<const float4*>(brow + e);
        acc += er[e] * b.x + er[e + 1] * b.y + er[e + 2] * b.z + er[e + 3] * b.w;
    }
    if (col < G3) g_embgi[c * G3 + col] = acc;
    else          g_fcemb[c * VV + (col - G3)] = acc;
}

// ---------------- shared HMMA machinery ----------------
__device__ __forceinline__ void copy_unit(uint32_t smb, int stage,
                                          const __nv_bfloat16* src, int t) {
    uint32_t dbase = smb + SM_B + stage * B_STAGE;
    const char* s = (const char*)src;
#pragma unroll
    for (int i = 0; i < 4; ++i) {
        int u = t + i * 256;               // 0..1023 16B quanta
        int n = u >> 3, c = u & 7;
        cp16(dbase + n * 144 + c * 16, s + (size_t)u * 16);
    }
}

__device__ __forceinline__ void mma_unit(uint32_t smb, int stage, int sp, int kc,
                                         int wy, int wx, int lane, float* acc) {
    uint32_t abase = smb + SM_A;
    uint32_t bbase = smb + SM_B + stage * B_STAGE;
    int arow = wy * 32 + (lane & 15);
    int akoff = ((lane >> 4) & 1) * 8;
    int brow = wx * 32 + ((lane >> 4) & 1) * 8 + (lane & 7);
    int bkoff = ((lane >> 3) & 1) * 8;
#pragma unroll
    for (int ks = 0; ks < 4; ++ks) {
        int kA = kc * 64 + ks * 16 + akoff;
        uint32_t b[4][2];
        {
            uint32_t r4[4];
            uint32_t bd = bbase + (brow * 72 + ks * 16 + bkoff) * 2;
            ldsm4(bd, r4);
            b[0][0] = r4[0]; b[0][1] = r4[1]; b[1][0] = r4[2]; b[1][1] = r4[3];
            ldsm4(bd + 16 * 72 * 2, r4);
            b[2][0] = r4[0]; b[2][1] = r4[1]; b[3][0] = r4[2]; b[3][1] = r4[3];
        }
        uint32_t ahi[2][4];
        ldsm4(abase + (arow * 520 + kA) * 2, ahi[0]);
        ldsm4(abase + ((arow + 16) * 520 + kA) * 2, ahi[1]);
        if (sp == 0) {
            uint32_t alo[2][4];
            ldsm4(abase + A_SPLIT + (arow * 520 + kA) * 2, alo[0]);
            ldsm4(abase + A_SPLIT + ((arow + 16) * 520 + kA) * 2, alo[1]);
#pragma unroll
            for (int mt = 0; mt < 2; ++mt)
#pragma unroll
                for (int nt = 0; nt < 4; ++nt) {
                    float* c = acc + (mt * 4 + nt) * 4;
                    mma16816(c, ahi[mt], b[nt]);
                    mma16816(c, alo[mt], b[nt]);
                }
        } else {
#pragma unroll
            for (int mt = 0; mt < 2; ++mt)
#pragma unroll
                for (int nt = 0; nt < 4; ++nt)
                    mma16816(acc + (mt * 4 + nt) * 4, ahi[mt], b[nt]);
        }
    }
}

__device__ __forceinline__ void packA(char* sm, const float* __restrict__ src, int t) {
#pragma unroll 4
    for (int i = 0; i < 32; ++i) {
        int idx = t + i * 256;
        int r = idx >> 7, kq = (idx & 127) * 4;
        float4 v = *(const float4*)(src + (size_t)r * HHD + kq);
        unsigned short h0, l0, h1, l1, h2, l2, h3, l3;
        bsplit(v.x, h0, l0); bsplit(v.y, h1, l1);
        bsplit(v.z, h2, l2); bsplit(v.w, h3, l3);
        char* d = sm + SM_A + (r * 520 + kq) * 2;
        *(uint32_t*)d = (uint32_t)h0 | ((uint32_t)h1 << 16);
        *(uint32_t*)(d + 4) = (uint32_t)h2 | ((uint32_t)h3 << 16);
        *(uint32_t*)(d + A_SPLIT) = (uint32_t)l0 | ((uint32_t)l1 << 16);
        *(uint32_t*)(d + A_SPLIT + 4) = (uint32_t)l2 | ((uint32_t)l3 << 16);
    }
}

// ---------------- ctx via HMMA: gctx/fcctx = enc @ W[:,128:640].T + bias ----------------
__global__ __launch_bounds__(256, 1)
void ctx_mma_kernel(const float* __restrict__ enc, const float* __restrict__ b_ih,
                    const float* __restrict__ b_hh, const float* __restrict__ fc_b) {
    extern __shared__ char smraw[];
    char* sm = smraw;
    uint32_t smb = smem_u32(sm);
    const int t = threadIdx.x, lane = t & 31, warp = t >> 5;
    const int wy = warp >> 2, wx = warp & 3;
    const int cta = blockIdx.x;

    packA(sm, enc + (size_t)cta * CROWS * HHD, t);
    float acc[32];
#pragma unroll
    for (int i = 0; i < 32; ++i) acc[i] = 0.f;
#pragma unroll
    for (int p = 0; p < 3; ++p) { copy_unit(smb, p, g_ctxpack + (size_t)p * 8192, t); CPCOMMIT(); }
#pragma unroll 1
    for (int u = 0; u < 208; ++u) {
        if (u < 206)      asm volatile("cp.async.wait_group 2;" ::: "memory");
        else if (u == 206) asm volatile("cp.async.wait_group 1;" ::: "memory");
        else               asm volatile("cp.async.wait_group 0;" ::: "memory");
        __syncthreads();
        int un = u + 3;
        if (un < 208) { copy_unit(smb, un & 3, g_ctxpack + (size_t)un * 8192, t); CPCOMMIT(); }
        int tl = u >> 4, rem = u & 15, kc = rem >> 1, sp = rem & 1;
        mma_unit(smb, u & 3, sp, kc, wy, wx, lane, acc);
        if (rem == 15) {
            // per-tile epilogue: add bias, store
#pragma unroll
            for (int mt = 0; mt < 2; ++mt)
#pragma unroll
                for (int nt = 0; nt < 4; ++nt)
#pragma unroll
                    for (int hh = 0; hh < 2; ++hh) {
                        int row = wy * 32 + mt * 16 + (lane >> 2) + hh * 8;
                        int ng = cta * CROWS + row;
                        int jcol = wx * 32 + nt * 8 + (lane & 3) * 2;
                        int base = (mt * 4 + nt) * 4 + hh * 2;
                        if (tl < 12) {
                            int j = tl * 128 + jcol;
                            float2 bi = *(const float2*)(b_ih + j);
                            float b0 = bi.x, b1 = bi.y;
                            if (j < 1024) {
                                float2 bh = *(const float2*)(b_hh + j);
                                b0 += bh.x; b1 += bh.y;
                            }
                            float2 v;
                            v.x = acc[base] + b0;
                            v.y = acc[base + 1] + b1;
                            *(float2*)(g_gctx + (size_t)ng * G3 + j) = v;
                        } else {
                            float2 fb = *(const float2*)(fc_b + jcol);
                            float2 v;
                            v.x = acc[base] + fb.x;
                            v.y = acc[base + 1] + fb.y;
                            *(float2*)(g_fcctx + (size_t)ng * VV + jcol) = v;
                        }
                    }
#pragma unroll
            for (int i = 0; i < 32; ++i) acc[i] = 0.f;
        }
    }
}

// ---------------- persistent decode kernel ----------------
__global__ __launch_bounds__(256, 1)
void decode_kernel(const float* __restrict__ encoded, const int* __restrict__ init_char,
                   const float* __restrict__ b_hh, float* __restrict__ out) {
    extern __shared__ char smraw[];
    char* sm = smraw;
    uint32_t smb = smem_u32(sm);
    const int t = threadIdx.x, lane = t & 31, warp = t >> 5;
    const int wy = warp >> 2, wx = warp & 3;
    const int cta = blockIdx.x;
    int* sch = (int*)(sm + SM_SCH);
    float* sbhn = (float*)(sm + SM_BHN);
    float* sargv = (float*)(sm + SM_ARGV);
    int* sargi = (int*)(sm + SM_ARGI);

    for (int i = t; i < 512; i += 256) sbhn[i] = b_hh[1024 + i];
    if (t < CROWS) sch[t] = init_char[cta * CROWS + t];
    packA(sm, encoded + (size_t)cta * CROWS * HHD, t);
    __syncthreads();

    for (int step = 0; step < SSTEPS; ++step) {
        float accr[32], accz[32], accn[32];
#pragma unroll
        for (int i = 0; i < 32; ++i) { accr[i] = 0.f; accz[i] = 0.f; accn[i] = 0.f; }
#pragma unroll
        for (int p = 0; p < 3; ++p) { copy_unit(smb, p, g_wpack + (size_t)p * 8192, t); CPCOMMIT(); }
#pragma unroll 1
        for (int u = 0; u < 208; ++u) {
            if (u < 206)      asm volatile("cp.async.wait_group 2;" ::: "memory");
            else if (u == 206) asm volatile("cp.async.wait_group 1;" ::: "memory");
            else               asm volatile("cp.async.wait_group 0;" ::: "memory");
            __syncthreads();
            int un = u + 3;
            if (un < 208) {
                const __nv_bfloat16* src = (un < 192)
                    ? g_wpack + (size_t)un * 8192
                    : g_fcpack + (size_t)(un - 192) * 8192;
                copy_unit(smb, un & 3, src, t);
                CPCOMMIT();
            }
            int tl = u >> 4, rem = u & 15, kc = rem >> 1, sp = rem & 1;
            int g = (tl < 12) ? (tl % 3) : 3;
            if (g == 0 || g == 3) mma_unit(smb, u & 3, sp, kc, wy, wx, lane, accr);
            else if (g == 1)      mma_unit(smb, u & 3, sp, kc, wy, wx, lane, accz);
            else                  mma_unit(smb, u & 3, sp, kc, wy, wx, lane, accn);

            if (rem == 15 && g == 2) {
                int jt = tl / 3;
                // ---- gate epilogue for this j-tile ----
#pragma unroll
                for (int mt = 0; mt < 2; ++mt)
#pragma unroll
                    for (int nt = 0; nt < 4; ++nt)
#pragma unroll
                        for (int hh = 0; hh < 2; ++hh) {
                            int row = wy * 32 + mt * 16 + (lane >> 2) + hh * 8;
                            int jcol = jt * 128 + wx * 32 + nt * 8 + (lane & 3) * 2;
                            int ng = cta * CROWS + row;
                            int cc = sch[row];
                            const float* gp = g_gctx + (size_t)ng * G3 + jcol;
                            const float* ep = g_embgi + (size_t)cc * G3 + jcol;
                            float2 gr = *(const float2*)gp;
                            float2 gz = *(const float2*)(gp + 512);
                            float2 gn = *(const float2*)(gp + 1024);
                            float2 er = *(const float2*)ep;
                            float2 ez = *(const float2*)(ep + 512);
                            float2 en = *(const float2*)(ep + 1024);
                            const char* ha = sm + SM_A + (row * 520 + jcol) * 2;
                            __nv_bfloat162 hv = *(const __nv_bfloat162*)ha;
                            __nv_bfloat162 lv = *(const __nv_bfloat162*)(ha + A_SPLIT);
                            float ho0 = __bfloat162float(hv.x) + __bfloat162float(lv.x);
                            float ho1 = __bfloat162float(hv.y) + __bfloat162float(lv.y);
                            int base = (mt * 4 + nt) * 4 + hh * 2;
                            float pr0 = gr.x + er.x + accr[base];
                            float pr1 = gr.y + er.y + accr[base + 1];
                            float pz0 = gz.x + ez.x + accz[base];
                            float pz1 = gz.y + ez.y + accz[base + 1];
                            float hn0 = accn[base] + sbhn[jcol];
                            float hn1 = accn[base + 1] + sbhn[jcol + 1];
                            float r0 = 1.f / (1.f + expf(-pr0));
                            float r1 = 1.f / (1.f + expf(-pr1));
                            float z0 = 1.f / (1.f + expf(-pz0));
                            float z1 = 1.f / (1.f + expf(-pz1));
                            float n0 = tanhf(gn.x + en.x + r0 * hn0);
                            float n1 = tanhf(gn.y + en.y + r1 * hn1);
                            float2 hnew;
                            hnew.x = (1.f - z0) * n0 + z0 * ho0;
                            hnew.y = (1.f - z1) * n1 + z1 * ho1;
                            *(float2*)(g_h + (size_t)ng * HHD + jcol) = hnew;
                        }
#pragma unroll
                for (int i = 0; i < 32; ++i) { accr[i] = 0.f; accz[i] = 0.f; accn[i] = 0.f; }
                if (tl == 11) {
                    __syncthreads();           // all g_h writes visible, A reads done
                    packA(sm, g_h + (size_t)cta * CROWS * HHD, t);   // A <- h_new
                    __syncthreads();
                }
            } else if (rem == 15 && g == 3) {
                // ---- fc epilogue: logits, out, argmax ----
                float best[4]; int bidx[4];
#pragma unroll
                for (int s = 0; s < 4; ++s) { best[s] = -1e30f; bidx[s] = 0; }
#pragma unroll
                for (int mt = 0; mt < 2; ++mt)
#pragma unroll
                    for (int hh = 0; hh < 2; ++hh) {
                        int slot = mt * 2 + hh;
                        int row = wy * 32 + mt * 16 + (lane >> 2) + hh * 8;
                        int ng = cta * CROWS + row;
                        int cc = sch[row];
#pragma unroll
                        for (int nt = 0; nt < 4; ++nt) {
                            int v = wx * 32 + nt * 8 + (lane & 3) * 2;
                            int base = (mt * 4 + nt) * 4 + hh * 2;
                            float2 fc = *(const float2*)(g_fcctx + (size_t)ng * VV + v);
                            float2 fe = *(const float2*)(g_fcemb + (size_t)cc * VV + v);
                            float p0 = accr[base] + fc.x + fe.x;
                            float p1 = accr[base + 1] + fc.y + fe.y;
                            float2 pv; pv.x = p0; pv.y = p1;
                            *(float2*)(out + ((size_t)ng * SSTEPS + step) * VV + v) = pv;
                            if (p0 > best[slot]) { best[slot] = p0; bidx[slot] = v; }
                            if (p1 > best[slot]) { best[slot] = p1; bidx[slot] = v + 1; }
                        }
                    }
#pragma unroll
                for (int s = 0; s < 4; ++s) {
#pragma unroll
                    for (int off = 1; off <= 2; off <<= 1) {
                        float ov = __shfl_xor_sync(0xffffffffu, best[s], off);
                        int oi = __shfl_xor_sync(0xffffffffu, bidx[s], off);
                        if (ov > best[s] || (ov == best[s] && oi < bidx[s])) { best[s] = ov; bidx[s] = oi; }
                    }
                }
                if ((lane & 3) == 0) {
#pragma unroll
                    for (int s = 0; s < 4; ++s) {
                        int row = wy * 32 + (s >> 1) * 16 + (lane >> 2) + (s & 1) * 8;
                        sargv[row * 4 + wx] = best[s];
                        sargi[row * 4 + wx] = bidx[s];
                    }
                }
                __syncthreads();
                if (t < CROWS) {
                    float bv = sargv[t * 4]; int bi = sargi[t * 4];
#pragma unroll
                    for (int wxi = 1; wxi < 4; ++wxi) {
                        float ov = sargv[t * 4 + wxi]; int oi = sargi[t * 4 + wxi];
                        if (ov > bv || (ov == bv && oi < bi)) { bv = ov; bi = oi; }
                    }
                    sch[t] = bi;
                }
            }
        }
    }
}

// ---------------------------------------------------------------------------
extern "C" void kernel_launch(void* const* d_in, const int* in_sizes, int n_in,
                              void* d_out, int out_size) {
    const float *encoded = 0, *emb_table = 0, *W_ih = 0, *W_hh = 0,
                *b_ih = 0, *b_hh = 0, *fc_W = 0, *fc_b = 0;
    const int* init_char = 0;
    for (int i = 0; i < n_in; ++i) {
        switch (in_sizes[i]) {
            case 8192 * 512:  encoded   = (const float*)d_in[i]; break;
            case 8192:        init_char = (const int*)d_in[i];   break;
            case 128 * 128:   emb_table = (const float*)d_in[i]; break;
            case 1536 * 640:  W_ih      = (const float*)d_in[i]; break;
            case 1536 * 512:  W_hh      = (const float*)d_in[i]; break;
            case 1536:        if (!b_ih) b_ih = (const float*)d_in[i];
                              else       b_hh = (const float*)d_in[i]; break;
            case 128 * 1152:  fc_W      = (const float*)d_in[i]; break;
            case 128:         fc_b      = (const float*)d_in[i]; break;
            default: break;
        }
    }
    float* out = (float*)d_out;

    cudaFuncSetAttribute(ctx_mma_kernel, cudaFuncAttributeMaxDynamicSharedMemorySize, SMEM_TOT);
    cudaFuncSetAttribute(decode_kernel, cudaFuncAttributeMaxDynamicSharedMemorySize, SMEM_TOT);

    pack_w_kernel<<<(G3 * HHD + 255) / 256, 256>>>(W_hh);
    pack_fc_kernel<<<(VV * HHD + 255) / 256, 256>>>(fc_W);
    pack_ctx_kernel<<<(1664 * 512 + 255) / 256, 256>>>(W_ih, fc_W);
    emb_kernel<<<dim3(13, 128), 128>>>(emb_table, W_ih, fc_W);
    ctx_mma_kernel<<<NCTA, 256, SMEM_TOT>>>(encoded, b_ih, b_hh, fc_b);
    decode_kernel<<<NCTA, 256, SMEM_TOT>>>(encoded, init_char, b_hh, out);
}

// round 7
// speedup vs baseline: 1.0899x; 1.0899x over previous
#include <cuda_runtime.h>
#include <cuda_bf16.h>
#include <math.h>
#include <stdint.h>

#define NS 8192
#define HHD 512
#define G3 1536
#define EE 128
#define VV 128
#define SSTEPS 32
#define NCTA 128
#define CROWS 64

// smem byte offsets
#define SM_A 0
#define A_SPLIT 66560          // 64*520*2 bytes per split
#define SM_B 133120
#define B_BUF 36864            // per buffer (2 splits)
#define B_SPL 18432            // 128*72*2
#define SM_BHN 206848          // 512 floats: b_hh n-gate part
#define SM_SCH 208896          // 64 ints
#define SM_ARGV 209152         // 256 floats
#define SM_ARGI 210176         // 256 ints
#define SMEM_TOT 211200

// ---------------- persistent device scratch ----------------
__device__ float g_gctx[(size_t)NS * G3];    // [n][1536], b_ih (+ b_hh r,z) folded
__device__ float g_fcctx[(size_t)NS * VV];   // [n][128], fc_b folded
__device__ float g_embgi[VV * G3];           // [c][1536]
__device__ float g_fcemb[VV * VV];           // [c][128]
__device__ float g_h[(size_t)NS * HHD];      // h_new staging (fp32)
__device__ __align__(128) __nv_bfloat16 g_wpack[12 * 8 * 2 * 8192];   // gh panels
__device__ __align__(128) __nv_bfloat16 g_fcpack[8 * 2 * 8192];       // fc panels
__device__ __align__(128) __nv_bfloat16 g_ctxpack[13 * 8 * 2 * 8192]; // ctx panels

// ---------------- small helpers ----------------
__device__ __forceinline__ uint32_t smem_u32(const void* p) {
    uint32_t a;
    asm("{ .reg .u64 t; cvta.to.shared.u64 t, %1; cvt.u32.u64 %0, t; }" : "=r"(a) : "l"(p));
    return a;
}
__device__ __forceinline__ void ldsm4(uint32_t addr, uint32_t r[4]) {
    asm volatile("ldmatrix.sync.aligned.m8n8.x4.shared.b16 {%0,%1,%2,%3}, [%4];"
        : "=r"(r[0]), "=r"(r[1]), "=r"(r[2]), "=r"(r[3]) : "r"(addr));
}
__device__ __forceinline__ void mma16816(float* c, const uint32_t a[4], const uint32_t b[2]) {
    asm volatile("mma.sync.aligned.m16n8k16.row.col.f32.bf16.bf16.f32 "
        "{%0,%1,%2,%3}, {%4,%5,%6,%7}, {%8,%9}, {%0,%1,%2,%3};"
        : "+f"(c[0]), "+f"(c[1]), "+f"(c[2]), "+f"(c[3])
        : "r"(a[0]), "r"(a[1]), "r"(a[2]), "r"(a[3]), "r"(b[0]), "r"(b[1]));
}
__device__ __forceinline__ void cp16(uint32_t dst, const void* src) {
    asm volatile("cp.async.cg.shared.global [%0], [%1], 16;" :: "r"(dst), "l"(src));
}
__device__ __forceinline__ void bsplit(float v, unsigned short& h, unsigned short& l) {
    __nv_bfloat16 bh = __float2bfloat16(v);
    __nv_bfloat16 bl = __float2bfloat16(v - __bfloat162float(bh));
    h = __bfloat16_as_ushort(bh);
    l = __bfloat16_as_ushort(bl);
}

// ---------------- prep kernels ----------------
__global__ void pack_w_kernel(const float* __restrict__ W_hh) {
    int idx = blockIdx.x * 256 + threadIdx.x;
    if (idx >= G3 * HHD) return;
    int R = idx >> 9, C = idx & 511;
    int g = R >> 9, rem = R & 511, jt = rem >> 7, n = rem & 127;
    int kc = C >> 6, k = C & 63;
    int tile = jt * 3 + g;
    unsigned short h, l;
    bsplit(W_hh[idx], h, l);
    size_t base = ((size_t)(tile * 8 + kc) * 2) * 8192 + n * 64 + k;
    g_wpack[base] = __ushort_as_bfloat16(h);
    g_wpack[base + 8192] = __ushort_as_bfloat16(l);
}

__global__ void pack_fc_kernel(const float* __restrict__ fc_W) {
    int idx = blockIdx.x * 256 + threadIdx.x;
    if (idx >= VV * HHD) return;
    int v = idx >> 9, C = idx & 511;
    int kc = C >> 6, k = C & 63;
    unsigned short h, l;
    bsplit(fc_W[(size_t)v * 1152 + 640 + C], h, l);
    size_t base = ((size_t)kc * 2) * 8192 + v * 64 + k;
    g_fcpack[base] = __ushort_as_bfloat16(h);
    g_fcpack[base + 8192] = __ushort_as_bfloat16(l);
}

// pack W_ih[:,128:640] (rows -> tiles 0..11) and fc_W[:,128:640] (tile 12)
__global__ void pack_ctx_kernel(const float* __restrict__ W_ih,
                                const float* __restrict__ fc_W) {
    int idx = blockIdx.x * 256 + threadIdx.x;
    if (idx >= 1664 * 512) return;
    int r = idx >> 9, k = idx & 511;
    float w = (r < G3) ? W_ih[(size_t)r * 640 + 128 + k]
                       : fc_W[(size_t)(r - G3) * 1152 + 128 + k];
    int tl = r >> 7, n = r & 127, kc = k >> 6, kk = k & 63;
    unsigned short h, l;
    bsplit(w, h, l);
    size_t base = ((size_t)(tl * 8 + kc) * 2) * 8192 + n * 64 + kk;
    g_ctxpack[base] = __ushort_as_bfloat16(h);
    g_ctxpack[base + 8192] = __ushort_as_bfloat16(l);
}

__global__ __launch_bounds__(128)
void emb_kernel(const float* __restrict__ emb_table,
                const float* __restrict__ W_ih,
                const float* __restrict__ fc_W) {
    __shared__ float er[EE];
    int c = blockIdx.y;
    int tx = threadIdx.x;
    er[tx] = emb_table[c * EE + tx];
    __syncthreads();
    int col = blockIdx.x * 128 + tx;   // [0, 1664)
    const float* brow = (col < G3) ? (W_ih + (size_t)col * 640)
                                   : (fc_W + (size_t)(col - G3) * 1152);
    float acc = 0.f;
#pragma unroll 8
    for (int e = 0; e < EE; e += 4) {
        float4 b = *reinterpret_cast<const float4*>(brow + e);
        acc += er[e] * b.x + er[e + 1] * b.y + er[e + 2] * b.z + er[e + 3] * b.w;
    }
    if (col < G3) g_embgi[c * G3 + col] = acc;
    else          g_fcemb[c * VV + (col - G3)] = acc;
}

// ---------------- HMMA machinery (round-4 structure, full 3-term) ----------------
__device__ __forceinline__ void copy_chunk(uint32_t smb, int buf, const __nv_bfloat16* src, int t) {
    uint32_t dbase = smb + SM_B + buf * B_BUF;
    const char* s = (const char*)src;
#pragma unroll
    for (int i = 0; i < 8; ++i) {
        int u = t + i * 256;
        int sp = u >> 10, rem = u & 1023, n = rem >> 3, c = rem & 7;
        cp16(dbase + sp * B_SPL + n * 144 + c * 16, s + sp * 16384 + n * 128 + c * 16);
    }
}

__device__ __forceinline__ void mma_chunk(uint32_t smb, int buf, int kc,
                                          int wy, int wx, int lane, float* acc) {
    uint32_t abase = smb + SM_A;
    uint32_t bbase = smb + SM_B + buf * B_BUF;
    int arow = wy * 32 + (lane & 7) + ((lane >> 3) & 1) * 8;
    int akoff = ((lane >> 4) & 1) * 8;
    int brow = wx * 32 + ((lane >> 4) & 1) * 8 + (lane & 7);
    int bkoff = ((lane >> 3) & 1) * 8;
#pragma unroll
    for (int ks = 0; ks < 4; ++ks) {
        int kA = kc * 64 + ks * 16 + akoff;
        uint32_t ahi[2][4], alo[2][4];
#pragma unroll
        for (int mt = 0; mt < 2; ++mt) {
            uint32_t ad = abase + ((arow + mt * 16) * 520 + kA) * 2;
            ldsm4(ad, ahi[mt]);
            ldsm4(ad + A_SPLIT, alo[mt]);
        }
        uint32_t bhi[4][2], blo[4][2];
#pragma unroll
        for (int p = 0; p < 2; ++p) {
            uint32_t bd = bbase + ((brow + p * 16) * 72 + ks * 16 + bkoff) * 2;
            uint32_t r4[4];
            ldsm4(bd, r4);
            bhi[2 * p][0] = r4[0]; bhi[2 * p][1] = r4[1];
            bhi[2 * p + 1][0] = r4[2]; bhi[2 * p + 1][1] = r4[3];
            ldsm4(bd + B_SPL, r4);
            blo[2 * p][0] = r4[0]; blo[2 * p][1] = r4[1];
            blo[2 * p + 1][0] = r4[2]; blo[2 * p + 1][1] = r4[3];
        }
#pragma unroll
        for (int mt = 0; mt < 2; ++mt)
#pragma unroll
            for (int nt = 0; nt < 4; ++nt) {
                float* c = acc + (mt * 4 + nt) * 4;
                mma16816(c, ahi[mt], bhi[nt]);
                mma16816(c, ahi[mt], blo[nt]);
                mma16816(c, alo[mt], bhi[nt]);
            }
    }
}

__device__ __forceinline__ void compute_tile(const __nv_bfloat16* Bsrc, float* acc,
                                             uint32_t smb, int wy, int wx, int lane, int t) {
#pragma unroll
    for (int i = 0; i < 32; ++i) acc[i] = 0.f;
    copy_chunk(smb, 0, Bsrc, t);
    asm volatile("cp.async.commit_group;" ::: "memory");
#pragma unroll 1
    for (int kc = 0; kc < 8; ++kc) {
        if (kc < 7) {
            copy_chunk(smb, (kc + 1) & 1, Bsrc + (size_t)(kc + 1) * 16384, t);
            asm volatile("cp.async.commit_group;" ::: "memory");
            asm volatile("cp.async.wait_group 1;" ::: "memory");
        } else {
            asm volatile("cp.async.wait_group 0;" ::: "memory");
        }
        __syncthreads();
        mma_chunk(smb, kc & 1, kc, wy, wx, lane, acc);
        __syncthreads();
    }
}

__device__ __forceinline__ void packA(char* sm, const float* __restrict__ src, int t) {
#pragma unroll 4
    for (int i = 0; i < 32; ++i) {
        int idx = t + i * 256;                 // 8192 float4
        int r = idx >> 7, kq = (idx & 127) * 4;
        float4 v = *(const float4*)(src + (size_t)r * HHD + kq);
        unsigned short h0, l0, h1, l1, h2, l2, h3, l3;
        bsplit(v.x, h0, l0); bsplit(v.y, h1, l1);
        bsplit(v.z, h2, l2); bsplit(v.w, h3, l3);
        char* d = sm + SM_A + (r * 520 + kq) * 2;
        *(uint32_t*)d = (uint32_t)h0 | ((uint32_t)h1 << 16);
        *(uint32_t*)(d + 4) = (uint32_t)h2 | ((uint32_t)h3 << 16);
        *(uint32_t*)(d + A_SPLIT) = (uint32_t)l0 | ((uint32_t)l1 << 16);
        *(uint32_t*)(d + A_SPLIT + 4) = (uint32_t)l2 | ((uint32_t)l3 << 16);
    }
}

// ---------------- ctx via HMMA: gctx/fcctx = enc @ W[:,128:640].T + bias ----------------
__global__ __launch_bounds__(256, 1)
void ctx_mma_kernel(const float* __restrict__ enc, const float* __restrict__ b_ih,
                    const float* __restrict__ b_hh, const float* __restrict__ fc_b) {
    extern __shared__ char smraw[];
    char* sm = smraw;
    uint32_t smb = smem_u32(sm);
    const int t = threadIdx.x, lane = t & 31, warp = t >> 5;
    const int wy = warp >> 2, wx = warp & 3;
    const int cta = blockIdx.x;

    packA(sm, enc + (size_t)cta * CROWS * HHD, t);
    __syncthreads();
    float acc[32];
#pragma unroll 1
    for (int tl = 0; tl < 13; ++tl) {
        compute_tile(g_ctxpack + (size_t)tl * 8 * 16384, acc, smb, wy, wx, lane, t);
#pragma unroll
        for (int mt = 0; mt < 2; ++mt)
#pragma unroll
            for (int nt = 0; nt < 4; ++nt)
#pragma unroll
                for (int hh = 0; hh < 2; ++hh) {
                    int row = wy * 32 + mt * 16 + (lane >> 2) + hh * 8;
                    int ng = cta * CROWS + row;
                    int jcol = wx * 32 + nt * 8 + (lane & 3) * 2;
                    int base = (mt * 4 + nt) * 4 + hh * 2;
                    if (tl < 12) {
                        int j = tl * 128 + jcol;
                        float2 bi = *(const float2*)(b_ih + j);
                        float b0 = bi.x, b1 = bi.y;
                        if (j < 1024) {
                            float2 bh = *(const float2*)(b_hh + j);
                            b0 += bh.x; b1 += bh.y;
                        }
                        float2 v;
                        v.x = acc[base] + b0;
                        v.y = acc[base + 1] + b1;
                        *(float2*)(g_gctx + (size_t)ng * G3 + j) = v;
                    } else {
                        float2 fb = *(const float2*)(fc_b + jcol);
                        float2 v;
                        v.x = acc[base] + fb.x;
                        v.y = acc[base + 1] + fb.y;
                        *(float2*)(g_fcctx + (size_t)ng * VV + jcol) = v;
                    }
                }
    }
}

// ---------------- persistent decode kernel ----------------
__global__ __launch_bounds__(256, 1)
void decode_kernel(const float* __restrict__ encoded, const int* __restrict__ init_char,
                   const float* __restrict__ b_hh, float* __restrict__ out) {
    extern __shared__ char smraw[];
    char* sm = smraw;
    uint32_t smb = smem_u32(sm);
    const int t = threadIdx.x, lane = t & 31, warp = t >> 5;
    const int wy = warp >> 2, wx = warp & 3;
    const int cta = blockIdx.x;
    int* sch = (int*)(sm + SM_SCH);
    float* sbhn = (float*)(sm + SM_BHN);
    float* sargv = (float*)(sm + SM_ARGV);
    int* sargi = (int*)(sm + SM_ARGI);

    for (int i = t; i < 512; i += 256) sbhn[i] = b_hh[1024 + i];
    if (t < CROWS) sch[t] = init_char[cta * CROWS + t];
    packA(sm, encoded + (size_t)cta * CROWS * HHD, t);
    __syncthreads();

    for (int step = 0; step < SSTEPS; ++step) {
        float str[32], stz[32], acc[32];
#pragma unroll 1
        for (int jt = 0; jt < 4; ++jt) {
            compute_tile(g_wpack + (size_t)(jt * 3 + 0) * 8 * 16384, str, smb, wy, wx, lane, t);
            compute_tile(g_wpack + (size_t)(jt * 3 + 1) * 8 * 16384, stz, smb, wy, wx, lane, t);
            compute_tile(g_wpack + (size_t)(jt * 3 + 2) * 8 * 16384, acc, smb, wy, wx, lane, t);
            // ---- gate epilogue for this j-tile ----
#pragma unroll
            for (int mt = 0; mt < 2; ++mt)
#pragma unroll
                for (int nt = 0; nt < 4; ++nt)
#pragma unroll
                    for (int hh = 0; hh < 2; ++hh) {
                        int row = wy * 32 + mt * 16 + (lane >> 2) + hh * 8;
                        int jcol = jt * 128 + wx * 32 + nt * 8 + (lane & 3) * 2;
                        int ng = cta * CROWS + row;
                        int cc = sch[row];
                        const float* gp = g_gctx + (size_t)ng * G3 + jcol;
                        const float* ep = g_embgi + (size_t)cc * G3 + jcol;
                        float2 gr = *(const float2*)gp;
                        float2 gz = *(const float2*)(gp + 512);
                        float2 gn = *(const float2*)(gp + 1024);
                        float2 er = *(const float2*)ep;
                        float2 ez = *(const float2*)(ep + 512);
                        float2 en = *(const float2*)(ep + 1024);
                        const char* ha = sm + SM_A + (row * 520 + jcol) * 2;
                        __nv_bfloat162 hv = *(const __nv_bfloat162*)ha;
                        __nv_bfloat162 lv = *(const __nv_bfloat162*)(ha + A_SPLIT);
                        float ho0 = __bfloat162float(hv.x) + __bfloat162float(lv.x);
                        float ho1 = __bfloat162float(hv.y) + __bfloat162float(lv.y);
                        int base = (mt * 4 + nt) * 4 + hh * 2;
                        float pr0 = gr.x + er.x + str[base];
                        float pr1 = gr.y + er.y + str[base + 1];
                        float pz0 = gz.x + ez.x + stz[base];
                        float pz1 = gz.y + ez.y + stz[base + 1];
                        float hn0 = acc[base] + sbhn[jcol];
                        float hn1 = acc[base + 1] + sbhn[jcol + 1];
                        float r0 = 1.f / (1.f + expf(-pr0));
                        float r1 = 1.f / (1.f + expf(-pr1));
                        float z0 = 1.f / (1.f + expf(-pz0));
                        float z1 = 1.f / (1.f + expf(-pz1));
                        float n0 = tanhf(gn.x + en.x + r0 * hn0);
                        float n1 = tanhf(gn.y + en.y + r1 * hn1);
                        float2 hnew;
                        hnew.x = (1.f - z0) * n0 + z0 * ho0;
                        hnew.y = (1.f - z1) * n1 + z1 * ho1;
                        *(float2*)(g_h + (size_t)ng * HHD + jcol) = hnew;
                    }
        }
        __syncthreads();                       // g_h writes visible; A reads done
        packA(sm, g_h + (size_t)cta * CROWS * HHD, t);   // A <- h_new
        __syncthreads();

        // ---- fc GEMM ----
        compute_tile(g_fcpack, acc, smb, wy, wx, lane, t);

        // ---- fc epilogue: logits, out, argmax ----
        float best[4]; int bidx[4];
#pragma unroll
        for (int s = 0; s < 4; ++s) { best[s] = -1e30f; bidx[s] = 0; }
#pragma unroll
        for (int mt = 0; mt < 2; ++mt)
#pragma unroll
            for (int hh = 0; hh < 2; ++hh) {
                int slot = mt * 2 + hh;
                int row = wy * 32 + mt * 16 + (lane >> 2) + hh * 8;
                int ng = cta * CROWS + row;
                int cc = sch[row];
#pragma unroll
                for (int nt = 0; nt < 4; ++nt) {
                    int v = wx * 32 + nt * 8 + (lane & 3) * 2;
                    int base = (mt * 4 + nt) * 4 + hh * 2;
                    float2 fc = *(const float2*)(g_fcctx + (size_t)ng * VV + v);
                    float2 fe = *(const float2*)(g_fcemb + (size_t)cc * VV + v);
                    float p0 = acc[base] + fc.x + fe.x;
                    float p1 = acc[base + 1] + fc.y + fe.y;
                    float2 pv; pv.x = p0; pv.y = p1;
                    *(float2*)(out + ((size_t)ng * SSTEPS + step) * VV + v) = pv;
                    if (p0 > best[slot]) { best[slot] = p0; bidx[slot] = v; }
                    if (p1 > best[slot]) { best[slot] = p1; bidx[slot] = v + 1; }
                }
            }
#pragma unroll
        for (int s = 0; s < 4; ++s) {
#pragma unroll
            for (int off = 1; off <= 2; off <<= 1) {
                float ov = __shfl_xor_sync(0xffffffffu, best[s], off);
                int oi = __shfl_xor_sync(0xffffffffu, bidx[s], off);
                if (ov > best[s] || (ov == best[s] && oi < bidx[s])) { best[s] = ov; bidx[s] = oi; }
            }
        }
        if ((lane & 3) == 0) {
#pragma unroll
            for (int s = 0; s < 4; ++s) {
                int row = wy * 32 + (s >> 1) * 16 + (lane >> 2) + (s & 1) * 8;
                sargv[row * 4 + wx] = best[s];
                sargi[row * 4 + wx] = bidx[s];
            }
        }
        __syncthreads();
        if (t < CROWS) {
            float bv = sargv[t * 4]; int bi = sargi[t * 4];
#pragma unroll
            for (int wxi = 1; wxi < 4; ++wxi) {
                float ov = sargv[t * 4 + wxi]; int oi = sargi[t * 4 + wxi];
                if (ov > bv || (ov == bv && oi < bi)) { bv = ov; bi = oi; }
            }
            sch[t] = bi;
        }
        __syncthreads();
    }
}

// ---------------------------------------------------------------------------
extern "C" void kernel_launch(void* const* d_in, const int* in_sizes, int n_in,
                              void* d_out, int out_size) {
    const float *encoded = 0, *emb_table = 0, *W_ih = 0, *W_hh = 0,
                *b_ih = 0, *b_hh = 0, *fc_W = 0, *fc_b = 0;
    const int* init_char = 0;
    for (int i = 0; i < n_in; ++i) {
        switch (in_sizes[i]) {
            case 8192 * 512:  encoded   = (const float*)d_in[i]; break;
            case 8192:        init_char = (const int*)d_in[i];   break;
            case 128 * 128:   emb_table = (const float*)d_in[i]; break;
            case 1536 * 640:  W_ih      = (const float*)d_in[i]; break;
            case 1536 * 512:  W_hh      = (const float*)d_in[i]; break;
            case 1536:        if (!b_ih) b_ih = (const float*)d_in[i];
                              else       b_hh = (const float*)d_in[i]; break;
            case 128 * 1152:  fc_W      = (const float*)d_in[i]; break;
            case 128:         fc_b      = (const float*)d_in[i]; break;
            default: break;
        }
    }
    float* out = (float*)d_out;

    cudaFuncSetAttribute(ctx_mma_kernel, cudaFuncAttributeMaxDynamicSharedMemorySize, SMEM_TOT);
    cudaFuncSetAttribute(decode_kernel, cudaFuncAttributeMaxDynamicSharedMemorySize, SMEM_TOT);

    pack_w_kernel<<<(G3 * HHD + 255) / 256, 256>>>(W_hh);
    pack_fc_kernel<<<(VV * HHD + 255) / 256, 256>>>(fc_W);
    pack_ctx_kernel<<<(1664 * 512 + 255) / 256, 256>>>(W_ih, fc_W);
    emb_kernel<<<dim3(13, 128), 128>>>(emb_table, W_ih, fc_W);
    ctx_mma_kernel<<<NCTA, 256, SMEM_TOT>>>(encoded, b_ih, b_hh, fc_b);
    decode_kernel<<<NCTA, 256, SMEM_TOT>>>(encoded, init_char, b_hh, out);
}

// round 8
// speedup vs baseline: 1.4797x; 1.3577x over previous
#include <cuda_runtime.h>
#include <cuda_fp16.h>
#include <math.h>
#include <stdint.h>

#define NS 8192
#define HHD 512
#define G3 1536
#define EE 128
#define VV 128
#define SSTEPS 32
#define NCTA 128
#define CROWS 64

// smem byte offsets
#define SM_A 0
#define A_SPLIT 66560          // 64*520*2 bytes per split
#define SM_B 133120
#define B_BUF 36864            // per buffer (holds up to 2 splits)
#define B_SPL 18432            // 128*72*2
#define SM_BHN 206848          // 512 floats: b_hh n-gate part
#define SM_SCH 208896          // 64 ints
#define SM_ARGV 209152         // 256 floats
#define SM_ARGI 210176         // 256 ints
#define SMEM_TOT 211200

// ---------------- persistent device scratch ----------------
__device__ float g_gctx[(size_t)NS * G3];    // [n][1536], b_ih (+ b_hh r,z) folded
__device__ float g_fcctx[(size_t)NS * VV];   // [n][128], fc_b folded
__device__ float g_embgi[VV * G3];           // [c][1536]
__device__ float g_fcemb[VV * VV];           // [c][128]
__device__ float g_h[(size_t)NS * HHD];      // h_new staging (fp32)
__device__ __align__(128) __half g_wpack[12 * 8 * 8192];        // gh panels, SINGLE fp16
__device__ __align__(128) __half g_fcpack[8 * 2 * 8192];        // fc panels, hi/lo fp16
__device__ __align__(128) __half g_ctxpack[13 * 8 * 2 * 8192];  // ctx panels, hi/lo fp16

// ---------------- small helpers ----------------
__device__ __forceinline__ uint32_t smem_u32(const void* p) {
    uint32_t a;
    asm("{ .reg .u64 t; cvta.to.shared.u64 t, %1; cvt.u32.u64 %0, t; }" : "=r"(a) : "l"(p));
    return a;
}
__device__ __forceinline__ void ldsm4(uint32_t addr, uint32_t r[4]) {
    asm volatile("ldmatrix.sync.aligned.m8n8.x4.shared.b16 {%0,%1,%2,%3}, [%4];"
        : "=r"(r[0]), "=r"(r[1]), "=r"(r[2]), "=r"(r[3]) : "r"(addr));
}
__device__ __forceinline__ void mma16816(float* c, const uint32_t a[4], const uint32_t b[2]) {
    asm volatile("mma.sync.aligned.m16n8k16.row.col.f32.f16.f16.f32 "
        "{%0,%1,%2,%3}, {%4,%5,%6,%7}, {%8,%9}, {%0,%1,%2,%3};"
        : "+f"(c[0]), "+f"(c[1]), "+f"(c[2]), "+f"(c[3])
        : "r"(a[0]), "r"(a[1]), "r"(a[2]), "r"(a[3]), "r"(b[0]), "r"(b[1]));
}
__device__ __forceinline__ void cp16(uint32_t dst, const void* src) {
    asm volatile("cp.async.cg.shared.global [%0], [%1], 16;" :: "r"(dst), "l"(src));
}
__device__ __forceinline__ void hsplit(float v, unsigned short& h, unsigned short& l) {
    __half hh = __float2half(v);
    __half hl = __float2half(v - __half2float(hh));
    h = __half_as_ushort(hh);
    l = __half_as_ushort(hl);
}

// ---------------- prep kernels ----------------
// gh panels: SINGLE fp16 per weight
__global__ void pack_w_kernel(const float* __restrict__ W_hh) {
    int idx = blockIdx.x * 256 + threadIdx.x;
    if (idx >= G3 * HHD) return;
    int R = idx >> 9, C = idx & 511;
    int g = R >> 9, rem = R & 511, jt = rem >> 7, n = rem & 127;
    int kc = C >> 6, k = C & 63;
    int tile = jt * 3 + g;
    size_t base = (size_t)(tile * 8 + kc) * 8192 + n * 64 + k;
    g_wpack[base] = __float2half(W_hh[idx]);
}

__global__ void pack_fc_kernel(const float* __restrict__ fc_W) {
    int idx = blockIdx.x * 256 + threadIdx.x;
    if (idx >= VV * HHD) return;
    int v = idx >> 9, C = idx & 511;
    int kc = C >> 6, k = C & 63;
    unsigned short h, l;
    hsplit(fc_W[(size_t)v * 1152 + 640 + C], h, l);
    size_t base = ((size_t)kc * 2) * 8192 + v * 64 + k;
    g_fcpack[base] = __ushort_as_half(h);
    g_fcpack[base + 8192] = __ushort_as_half(l);
}

// pack W_ih[:,128:640] (rows -> tiles 0..11) and fc_W[:,128:640] (tile 12)
__global__ void pack_ctx_kernel(const float* __restrict__ W_ih,
                                const float* __restrict__ fc_W) {
    int idx = blockIdx.x * 256 + threadIdx.x;
    if (idx >= 1664 * 512) return;
    int r = idx >> 9, k = idx & 511;
    float w = (r < G3) ? W_ih[(size_t)r * 640 + 128 + k]
                       : fc_W[(size_t)(r - G3) * 1152 + 128 + k];
    int tl = r >> 7, n = r & 127, kc = k >> 6, kk = k & 63;
    unsigned short h, l;
    hsplit(w, h, l);
    size_t base = ((size_t)(tl * 8 + kc) * 2) * 8192 + n * 64 + kk;
    g_ctxpack[base] = __ushort_as_half(h);
    g_ctxpack[base + 8192] = __ushort_as_half(l);
}

__global__ __launch_bounds__(128)
void emb_kernel(const float* __restrict__ emb_table,
                const float* __restrict__ W_ih,
                const float* __restrict__ fc_W) {
    __shared__ float er[EE];
    int c = blockIdx.y;
    int tx = threadIdx.x;
    er[tx] = emb_table[c * EE + tx];
    __syncthreads();
    int col = blockIdx.x * 128 + tx;   // [0, 1664)
    const float* brow = (col < G3) ? (W_ih + (size_t)col * 640)
                                   : (fc_W + (size_t)(col - G3) * 1152);
    float acc = 0.f;
#pragma unroll 8
    for (int e = 0; e < EE; e += 4) {
        float4 b = *reinterpret_cast<const float4*>(brow + e);
        acc += er[e] * b.x + er[e + 1] * b.y + er[e + 2] * b.z + er[e + 3] * b.w;
    }
    if (col < G3) g_embgi[c * G3 + col] = acc;
    else          g_fcemb[c * VV + (col - G3)] = acc;
}

// ---------------- HMMA machinery ----------------
// copy one 16KB split into stage buffer
__device__ __forceinline__ void copy_split(uint32_t dbase, const __half* src, int t) {
    const char* s = (const char*)src;
#pragma unroll
    for (int i = 0; i < 4; ++i) {
        int u = t + i * 256;
        int n = u >> 3, c = u & 7;
        cp16(dbase + n * 144 + c * 16, s + (size_t)u * 16);
    }
}
__device__ __forceinline__ void copy_chunk1(uint32_t smb, int buf, const __half* src, int t) {
    copy_split(smb + SM_B + buf * B_BUF, src, t);
}
__device__ __forceinline__ void copy_chunk2(uint32_t smb, int buf, const __half* src, int t) {
    copy_split(smb + SM_B + buf * B_BUF, src, t);
    copy_split(smb + SM_B + buf * B_BUF + B_SPL, src + 8192, t);
}

// gh: B single split, A split 2-ways -> 2 products
__device__ __forceinline__ void mma_chunk_g(uint32_t smb, int buf, int kc,
                                            int wy, int wx, int lane, float* acc) {
    uint32_t abase = smb + SM_A;
    uint32_t bbase = smb + SM_B + buf * B_BUF;
    int arow = wy * 32 + (lane & 7) + ((lane >> 3) & 1) * 8;
    int akoff = ((lane >> 4) & 1) * 8;
    int brow = wx * 32 + ((lane >> 4) & 1) * 8 + (lane & 7);
    int bkoff = ((lane >> 3) & 1) * 8;
#pragma unroll
    for (int ks = 0; ks < 4; ++ks) {
        int kA = kc * 64 + ks * 16 + akoff;
        uint32_t ahi[2][4], alo[2][4];
#pragma unroll
        for (int mt = 0; mt < 2; ++mt) {
            uint32_t ad = abase + ((arow + mt * 16) * 520 + kA) * 2;
            ldsm4(ad, ahi[mt]);
            ldsm4(ad + A_SPLIT, alo[mt]);
        }
        uint32_t b[4][2];
#pragma unroll
        for (int p = 0; p < 2; ++p) {
            uint32_t bd = bbase + ((brow + p * 16) * 72 + ks * 16 + bkoff) * 2;
            uint32_t r4[4];
            ldsm4(bd, r4);
            b[2 * p][0] = r4[0]; b[2 * p][1] = r4[1];
            b[2 * p + 1][0] = r4[2]; b[2 * p + 1][1] = r4[3];
        }
#pragma unroll
        for (int mt = 0; mt < 2; ++mt)
#pragma unroll
            for (int nt = 0; nt < 4; ++nt) {
                float* c = acc + (mt * 4 + nt) * 4;
                mma16816(c, ahi[mt], b[nt]);
                mma16816(c, alo[mt], b[nt]);
            }
    }
}

// fc/ctx: B split 2-ways, A split 2-ways -> 3 products
__device__ __forceinline__ void mma_chunk_f(uint32_t smb, int buf, int kc,
                                            int wy, int wx, int lane, float* acc) {
    uint32_t abase = smb + SM_A;
    uint32_t bbase = smb + SM_B + buf * B_BUF;
    int arow = wy * 32 + (lane & 7) + ((lane >> 3) & 1) * 8;
    int akoff = ((lane >> 4) & 1) * 8;
    int brow = wx * 32 + ((lane >> 4) & 1) * 8 + (lane & 7);
    int bkoff = ((lane >> 3) & 1) * 8;
#pragma unroll
    for (int ks = 0; ks < 4; ++ks) {
        int kA = kc * 64 + ks * 16 + akoff;
        uint32_t ahi[2][4], alo[2][4];
#pragma unroll
        for (int mt = 0; mt < 2; ++mt) {
            uint32_t ad = abase + ((arow + mt * 16) * 520 + kA) * 2;
            ldsm4(ad, ahi[mt]);
            ldsm4(ad + A_SPLIT, alo[mt]);
        }
        uint32_t bhi[4][2], blo[4][2];
#pragma unroll
        for (int p = 0; p < 2; ++p) {
            uint32_t bd = bbase + ((brow + p * 16) * 72 + ks * 16 + bkoff) * 2;
            uint32_t r4[4];
            ldsm4(bd, r4);
            bhi[2 * p][0] = r4[0]; bhi[2 * p][1] = r4[1];
            bhi[2 * p + 1][0] = r4[2]; bhi[2 * p + 1][1] = r4[3];
            ldsm4(bd + B_SPL, r4);
            blo[2 * p][0] = r4[0]; blo[2 * p][1] = r4[1];
            blo[2 * p + 1][0] = r4[2]; blo[2 * p + 1][1] = r4[3];
        }
#pragma unroll
        for (int mt = 0; mt < 2; ++mt)
#pragma unroll
            for (int nt = 0; nt < 4; ++nt) {
                float* c = acc + (mt * 4 + nt) * 4;
                mma16816(c, ahi[mt], bhi[nt]);
                mma16816(c, ahi[mt], blo[nt]);
                mma16816(c, alo[mt], bhi[nt]);
            }
    }
}

// gh tile: 8 chunks x 8192 halves, single split
__device__ __forceinline__ void compute_tile_g(const __half* Bsrc, float* acc,
                                               uint32_t smb, int wy, int wx, int lane, int t) {
#pragma unroll
    for (int i = 0; i < 32; ++i) acc[i] = 0.f;
    copy_chunk1(smb, 0, Bsrc, t);
    asm volatile("cp.async.commit_group;" ::: "memory");
#pragma unroll 1
    for (int kc = 0; kc < 8; ++kc) {
        if (kc < 7) {
            copy_chunk1(smb, (kc + 1) & 1, Bsrc + (size_t)(kc + 1) * 8192, t);
            asm volatile("cp.async.commit_group;" ::: "memory");
            asm volatile("cp.async.wait_group 1;" ::: "memory");
        } else {
            asm volatile("cp.async.wait_group 0;" ::: "memory");
        }
        __syncthreads();
        mma_chunk_g(smb, kc & 1, kc, wy, wx, lane, acc);
        __syncthreads();
    }
}

// fc/ctx tile: 8 chunks x 16384 halves, 2 splits
__device__ __forceinline__ void compute_tile_f(const __half* Bsrc, float* acc,
                                               uint32_t smb, int wy, int wx, int lane, int t) {
#pragma unroll
    for (int i = 0; i < 32; ++i) acc[i] = 0.f;
    copy_chunk2(smb, 0, Bsrc, t);
    asm volatile("cp.async.commit_group;" ::: "memory");
#pragma unroll 1
    for (int kc = 0; kc < 8; ++kc) {
        if (kc < 7) {
            copy_chunk2(smb, (kc + 1) & 1, Bsrc + (size_t)(kc + 1) * 16384, t);
            asm volatile("cp.async.commit_group;" ::: "memory");
            asm volatile("cp.async.wait_group 1;" ::: "memory");
        } else {
            asm volatile("cp.async.wait_group 0;" ::: "memory");
        }
        __syncthreads();
        mma_chunk_f(smb, kc & 1, kc, wy, wx, lane, acc);
        __syncthreads();
    }
}

__device__ __forceinline__ void packA(char* sm, const float* __restrict__ src, int t) {
#pragma unroll 4
    for (int i = 0; i < 32; ++i) {
        int idx = t + i * 256;                 // 8192 float4
        int r = idx >> 7, kq = (idx & 127) * 4;
        float4 v = *(const float4*)(src + (size_t)r * HHD + kq);
        unsigned short h0, l0, h1, l1, h2, l2, h3, l3;
        hsplit(v.x, h0, l0); hsplit(v.y, h1, l1);
        hsplit(v.z, h2, l2); hsplit(v.w, h3, l3);
        char* d = sm + SM_A + (r * 520 + kq) * 2;
        *(uint32_t*)d = (uint32_t)h0 | ((uint32_t)h1 << 16);
        *(uint32_t*)(d + 4) = (uint32_t)h2 | ((uint32_t)h3 << 16);
        *(uint32_t*)(d + A_SPLIT) = (uint32_t)l0 | ((uint32_t)l1 << 16);
        *(uint32_t*)(d + A_SPLIT + 4) = (uint32_t)l2 | ((uint32_t)l3 << 16);
    }
}

// ---------------- ctx via HMMA: gctx/fcctx = enc @ W[:,128:640].T + bias ----------------
__global__ __launch_bounds__(256, 1)
void ctx_mma_kernel(const float* __restrict__ enc, const float* __restrict__ b_ih,
                    const float* __restrict__ b_hh, const float* __restrict__ fc_b) {
    extern __shared__ char smraw[];
    char* sm = smraw;
    uint32_t smb = smem_u32(sm);
    const int t = threadIdx.x, lane = t & 31, warp = t >> 5;
    const int wy = warp >> 2, wx = warp & 3;
    const int cta = blockIdx.x;

    packA(sm, enc + (size_t)cta * CROWS * HHD, t);
    __syncthreads();
    float acc[32];
#pragma unroll 1
    for (int tl = 0; tl < 13; ++tl) {
        compute_tile_f(g_ctxpack + (size_t)tl * 8 * 16384, acc, smb, wy, wx, lane, t);
#pragma unroll
        for (int mt = 0; mt < 2; ++mt)
#pragma unroll
            for (int nt = 0; nt < 4; ++nt)
#pragma unroll
                for (int hh = 0; hh < 2; ++hh) {
                    int row = wy * 32 + mt * 16 + (lane >> 2) + hh * 8;
                    int ng = cta * CROWS + row;
                    int jcol = wx * 32 + nt * 8 + (lane & 3) * 2;
                    int base = (mt * 4 + nt) * 4 + hh * 2;
                    if (tl < 12) {
                        int j = tl * 128 + jcol;
                        float2 bi = *(const float2*)(b_ih + j);
                        float b0 = bi.x, b1 = bi.y;
                        if (j < 1024) {
                            float2 bh = *(const float2*)(b_hh + j);
                            b0 += bh.x; b1 += bh.y;
                        }
                        float2 v;
                        v.x = acc[base] + b0;
                        v.y = acc[base + 1] + b1;
                        *(float2*)(g_gctx + (size_t)ng * G3 + j) = v;
                    } else {
                        float2 fb = *(const float2*)(fc_b + jcol);
                        float2 v;
                        v.x = acc[base] + fb.x;
                        v.y = acc[base + 1] + fb.y;
                        *(float2*)(g_fcctx + (size_t)ng * VV + jcol) = v;
                    }
                }
    }
}

// ---------------- persistent decode kernel ----------------
__global__ __launch_bounds__(256, 1)
void decode_kernel(const float* __restrict__ encoded, const int* __restrict__ init_char,
                   const float* __restrict__ b_hh, float* __restrict__ out) {
    extern __shared__ char smraw[];
    char* sm = smraw;
    uint32_t smb = smem_u32(sm);
    const int t = threadIdx.x, lane = t & 31, warp = t >> 5;
    const int wy = warp >> 2, wx = warp & 3;
    const int cta = blockIdx.x;
    int* sch = (int*)(sm + SM_SCH);
    float* sbhn = (float*)(sm + SM_BHN);
    float* sargv = (float*)(sm + SM_ARGV);
    int* sargi = (int*)(sm + SM_ARGI);

    for (int i = t; i < 512; i += 256) sbhn[i] = b_hh[1024 + i];
    if (t < CROWS) sch[t] = init_char[cta * CROWS + t];
    packA(sm, encoded + (size_t)cta * CROWS * HHD, t);
    __syncthreads();

    for (int step = 0; step < SSTEPS; ++step) {
        float str[32], stz[32], acc[32];
#pragma unroll 1
        for (int jt = 0; jt < 4; ++jt) {
            compute_tile_g(g_wpack + (size_t)(jt * 3 + 0) * 8 * 8192, str, smb, wy, wx, lane, t);
            compute_tile_g(g_wpack + (size_t)(jt * 3 + 1) * 8 * 8192, stz, smb, wy, wx, lane, t);
            compute_tile_g(g_wpack + (size_t)(jt * 3 + 2) * 8 * 8192, acc, smb, wy, wx, lane, t);
            // ---- gate epilogue for this j-tile ----
#pragma unroll
            for (int mt = 0; mt < 2; ++mt)
#pragma unroll
                for (int nt = 0; nt < 4; ++nt)
#pragma unroll
                    for (int hh = 0; hh < 2; ++hh) {
                        int row = wy * 32 + mt * 16 + (lane >> 2) + hh * 8;
                        int jcol = jt * 128 + wx * 32 + nt * 8 + (lane & 3) * 2;
                        int ng = cta * CROWS + row;
                        int cc = sch[row];
                        const float* gp = g_gctx + (size_t)ng * G3 + jcol;
                        const float* ep = g_embgi + (size_t)cc * G3 + jcol;
                        float2 gr = *(const float2*)gp;
                        float2 gz = *(const float2*)(gp + 512);
                        float2 gn = *(const float2*)(gp + 1024);
                        float2 er = *(const float2*)ep;
                        float2 ez = *(const float2*)(ep + 512);
                        float2 en = *(const float2*)(ep + 1024);
                        const char* ha = sm + SM_A + (row * 520 + jcol) * 2;
                        __half2 hv = *(const __half2*)ha;
                        __half2 lv = *(const __half2*)(ha + A_SPLIT);
                        float ho0 = __half2float(__low2half(hv)) + __half2float(__low2half(lv));
                        float ho1 = __half2float(__high2half(hv)) + __half2float(__high2half(lv));
                        int base = (mt * 4 + nt) * 4 + hh * 2;
                        float pr0 = gr.x + er.x + str[base];
                        float pr1 = gr.y + er.y + str[base + 1];
                        float pz0 = gz.x + ez.x + stz[base];
                        float pz1 = gz.y + ez.y + stz[base + 1];
                        float hn0 = acc[base] + sbhn[jcol];
                        float hn1 = acc[base + 1] + sbhn[jcol + 1];
                        float r0 = 1.f / (1.f + expf(-pr0));
                        float r1 = 1.f / (1.f + expf(-pr1));
                        float z0 = 1.f / (1.f + expf(-pz0));
                        float z1 = 1.f / (1.f + expf(-pz1));
                        float n0 = tanhf(gn.x + en.x + r0 * hn0);
                        float n1 = tanhf(gn.y + en.y + r1 * hn1);
                        float2 hnew;
                        hnew.x = (1.f - z0) * n0 + z0 * ho0;
                        hnew.y = (1.f - z1) * n1 + z1 * ho1;
                        *(float2*)(g_h + (size_t)ng * HHD + jcol) = hnew;
                    }
        }
        __syncthreads();                       // g_h writes visible; A reads done
        packA(sm, g_h + (size_t)cta * CROWS * HHD, t);   // A <- h_new
        __syncthreads();

        // ---- fc GEMM (full 3-product fp16: argmax-critical) ----
        compute_tile_f(g_fcpack, acc, smb, wy, wx, lane, t);

        // ---- fc epilogue: logits, out, argmax ----
        float best[4]; int bidx[4];
#pragma unroll
        for (int s = 0; s < 4; ++s) { best[s] = -1e30f; bidx[s] = 0; }
#pragma unroll
        for (int mt = 0; mt < 2; ++mt)
#pragma unroll
            for (int hh = 0; hh < 2; ++hh) {
                int slot = mt * 2 + hh;
                int row = wy * 32 + mt * 16 + (lane >> 2) + hh * 8;
                int ng = cta * CROWS + row;
                int cc = sch[row];
#pragma unroll
                for (int nt = 0; nt < 4; ++nt) {
                    int v = wx * 32 + nt * 8 + (lane & 3) * 2;
                    int base = (mt * 4 + nt) * 4 + hh * 2;
                    float2 fc = *(const float2*)(g_fcctx + (size_t)ng * VV + v);
                    float2 fe = *(const float2*)(g_fcemb + (size_t)cc * VV + v);
                    float p0 = acc[base] + fc.x + fe.x;
                    float p1 = acc[base + 1] + fc.y + fe.y;
                    float2 pv; pv.x = p0; pv.y = p1;
                    *(float2*)(out + ((size_t)ng * SSTEPS + step) * VV + v) = pv;
                    if (p0 > best[slot]) { best[slot] = p0; bidx[slot] = v; }
                    if (p1 > best[slot]) { best[slot] = p1; bidx[slot] = v + 1; }
                }
            }
#pragma unroll
        for (int s = 0; s < 4; ++s) {
#pragma unroll
            for (int off = 1; off <= 2; off <<= 1) {
                float ov = __shfl_xor_sync(0xffffffffu, best[s], off);
                int oi = __shfl_xor_sync(0xffffffffu, bidx[s], off);
                if (ov > best[s] || (ov == best[s] && oi < bidx[s])) { best[s] = ov; bidx[s] = oi; }
            }
        }
        if ((lane & 3) == 0) {
#pragma unroll
            for (int s = 0; s < 4; ++s) {
                int row = wy * 32 + (s >> 1) * 16 + (lane >> 2) + (s & 1) * 8;
                sargv[row * 4 + wx] = best[s];
                sargi[row * 4 + wx] = bidx[s];
            }
        }
        __syncthreads();
        if (t < CROWS) {
            float bv = sargv[t * 4]; int bi = sargi[t * 4];
#pragma unroll
            for (int wxi = 1; wxi < 4; ++wxi) {
                float ov = sargv[t * 4 + wxi]; int oi = sargi[t * 4 + wxi];
                if (ov > bv || (ov == bv && oi < bi)) { bv = ov; bi = oi; }
            }
            sch[t] = bi;
        }
        __syncthreads();
    }
}

// ---------------------------------------------------------------------------
extern "C" void kernel_launch(void* const* d_in, const int* in_sizes, int n_in,
                              void* d_out, int out_size) {
    const float *encoded = 0, *emb_table = 0, *W_ih = 0, *W_hh = 0,
                *b_ih = 0, *b_hh = 0, *fc_W = 0, *fc_b = 0;
    const int* init_char = 0;
    for (int i = 0; i < n_in; ++i) {
        switch (in_sizes[i]) {
            case 8192 * 512:  encoded   = (const float*)d_in[i]; break;
            case 8192:        init_char = (const int*)d_in[i];   break;
            case 128 * 128:   emb_table = (const float*)d_in[i]; break;
            case 1536 * 640:  W_ih      = (const float*)d_in[i]; break;
            case 1536 * 512:  W_hh      = (const float*)d_in[i]; break;
            case 1536:        if (!b_ih) b_ih = (const float*)d_in[i];
                              else       b_hh = (const float*)d_in[i]; break;
            case 128 * 1152:  fc_W      = (const float*)d_in[i]; break;
            case 128:         fc_b      = (const float*)d_in[i]; break;
            default: break;
        }
    }
    float* out = (float*)d_out;

    cudaFuncSetAttribute(ctx_mma_kernel, cudaFuncAttributeMaxDynamicSharedMemorySize, SMEM_TOT);
    cudaFuncSetAttribute(decode_kernel, cudaFuncAttributeMaxDynamicSharedMemorySize, SMEM_TOT);

    pack_w_kernel<<<(G3 * HHD + 255) / 256, 256>>>(W_hh);
    pack_fc_kernel<<<(VV * HHD + 255) / 256, 256>>>(fc_W);
    pack_ctx_kernel<<<(1664 * 512 + 255) / 256, 256>>>(W_ih, fc_W);
    emb_kernel<<<dim3(13, 128), 128>>>(emb_table, W_ih, fc_W);
    ctx_mma_kernel<<<NCTA, 256, SMEM_TOT>>>(encoded, b_ih, b_hh, fc_b);
    decode_kernel<<<NCTA, 256, SMEM_TOT>>>(encoded, init_char, b_hh, out);
}